// round 8
// baseline (speedup 1.0000x reference)
#include <cuda_runtime.h>
#include <cuda_bf16.h>
#include <cstdint>
#include <math.h>

// Problem constants (fixed by the reference setup_inputs)
#define BB 256   // batches
#define AA 64    // atoms
#define EE 128   // edges
#define KK 6     // neighbors
#define HH 256   // hidden

#define HBLK 64                   // H columns per CTA tile
#define ROW4 (HBLK / 4)           // 16 float4 per tile row
#define TILES_PER_B (HH / HBLK)   // 4
#define NTILES (BB * TILES_PER_B) // 1024 CTAs, one tile each
#define NTHREADS 256
#define TILE_F4 (EE * ROW4)       // 2048 float4 per tile

__global__ __launch_bounds__(NTHREADS)
void DirectedEdgeMessage_89885075571226_kernel(
    const float* __restrict__ rep,     // [B, E, H]
    const int*   __restrict__ pairs,   // [B, E, 2]
    const int*   __restrict__ nbrs,    // [B, E, K]
    const float* __restrict__ xyz,     // [B, A, 3]
    float*       __restrict__ out)     // [B, E, H]
{
    __shared__ float s_dist[EE];       // per-edge distance weight
    __shared__ int   s_nb[EE * KK];    // neighbor indices

    const int tid = threadIdx.x;
    const int b   = blockIdx.x >> 2;   // TILES_PER_B = 4
    const int hb  = blockIdx.x & 3;

    // ---- Tiny staging: dist + neighbor indices (3.5 KB smem) ----
    if (tid < EE) {
        const int e  = tid;
        const int p0 = __ldg(&pairs[(b * EE + e) * 2 + 0]);
        const int p1 = __ldg(&pairs[(b * EE + e) * 2 + 1]);
        const float* x0 = xyz + ((size_t)b * AA + p0) * 3;
        const float* x1 = xyz + ((size_t)b * AA + p1) * 3;
        const float dx = __ldg(x0 + 0) - __ldg(x1 + 0);
        const float dy = __ldg(x0 + 1) - __ldg(x1 + 1);
        const float dz = __ldg(x0 + 2) - __ldg(x1 + 2);
        const float d2 = dx * dx + dy * dy + dz * dz;
        const float inv = 1.0f / d2;
        s_dist[e] = isinf(inv) ? 0.0f : inv;
    }
    // 768 ints, 256 threads: 3 each (coalesced)
    {
        const int* nb = nbrs + (size_t)b * EE * KK;
        #pragma unroll
        for (int i = tid; i < EE * KK; i += NTHREADS)
            s_nb[i] = __ldg(&nb[i]);
    }
    __syncthreads();

    // ---- Gather 6 neighbor rows straight from GMEM (L1-cached reuse) ----
    const float4* __restrict__ repv =
        (const float4*)(rep + (size_t)b * EE * HH + hb * HBLK);   // row stride HH/4
    float4* __restrict__ outv =
        (float4*)(out + (size_t)b * EE * HH + hb * HBLK);

    #pragma unroll
    for (int p = 0; p < TILE_F4 / NTHREADS; p++) {   // 8 iters
        const int i  = tid + p * NTHREADS;
        const int e  = i >> 4;                       // 16 lanes per edge row
        const int h4 = i & 15;                       // 256B contiguous per (e,k)
        const int* n = s_nb + e * KK;
        float4 acc = make_float4(0.f, 0.f, 0.f, 0.f);
        #pragma unroll
        for (int k = 0; k < KK; k++) {
            const int   nk = n[k];                   // smem broadcast
            const float w  = s_dist[nk];             // smem broadcast
            const float4 v = __ldg(&repv[(size_t)nk * (HH / 4) + h4]);
            acc.x = fmaf(w, v.x, acc.x);
            acc.y = fmaf(w, v.y, acc.y);
            acc.z = fmaf(w, v.z, acc.z);
            acc.w = fmaf(w, v.w, acc.w);
        }
        outv[(size_t)e * (HH / 4) + h4] = acc;
    }
}

extern "C" void kernel_launch(void* const* d_in, const int* in_sizes, int n_in,
                              void* d_out, int out_size)
{
    const float* rep   = (const float*)d_in[0];  // bond_representations [1,B,E,H]
    const int*   pairs = (const int*)  d_in[1];  // bond_pairs [B,E,2]
    const int*   nbrs  = (const int*)  d_in[2];  // bond_neighbors [B,E,K]
    const float* xyz   = (const float*)d_in[3];  // xyz [B,A,3]
    float*       out   = (float*)d_out;          // [1,B,E,H]

    DirectedEdgeMessage_89885075571226_kernel<<<NTILES, NTHREADS>>>(
        rep, pairs, nbrs, xyz, out);
}